// round 1
// baseline (speedup 1.0000x reference)
#include <cuda_runtime.h>

#define BB 8
#define LL 2048
#define DD 256
#define BM 64
#define BN 64

#define KSTRIDE 257   // padded K-tile row stride (floats) to break bank conflicts
#define PSTRIDE 65    // padded P-tile row stride

// 16 MB scratch for itr_attn (static device array: allocation-free)
__device__ float g_attn[(size_t)BB * LL * DD];

// ---------------------------------------------------------------------------
// Kernel A: flash-style internal attention.
//  logits A[i,j] = s_u[j] + sum_d (x_i,d * wp_d) * x_j,d      (s_m dropped:
//  it is constant along softmax axis j and cancels)
//  out = softmax_j(A) @ x
// grid (L/BM, B), 256 threads. Thread (ty=tid>>4, tx=tid&15) owns a 4x4 S
// microtile (rows 4ty+r, cols 4tx+c) and O cols d = 4tx+q+64c (q<4,c<4).
// ---------------------------------------------------------------------------
__global__ __launch_bounds__(256, 1)
void attn_kernel(const float* __restrict__ x, const float* __restrict__ w_itr)
{
    extern __shared__ float sm[];
    float* Ys = sm;                       // [64][256]
    float* Ks = Ys + BM * DD;             // [64][KSTRIDE]
    float* Ps = Ks + BN * KSTRIDE;        // [64][PSTRIDE]
    float* su = Ps + BM * PSTRIDE;        // [64]

    const int b   = blockIdx.y;
    const int q0  = blockIdx.x * BM;
    const int tid = threadIdx.x;
    const int tx  = tid & 15;
    const int ty  = tid >> 4;

    const float* xb = x + (size_t)b * LL * DD;
    const float* wu = w_itr;              // [0:D)
    const float* wp = w_itr + 2 * DD;     // [2D:3D)

    const float4* wp4 = reinterpret_cast<const float4*>(wp);
    const float4* wu4 = reinterpret_cast<const float4*>(wu);

    // Y = x_q * wp (resident for whole CTA)
    for (int idx = tid; idx < BM * (DD / 4); idx += 256) {
        int i = idx >> 6, d4 = idx & 63;
        float4 xv = reinterpret_cast<const float4*>(xb + (size_t)(q0 + i) * DD)[d4];
        float4 wv = wp4[d4];
        float* yr = Ys + i * DD + d4 * 4;
        yr[0] = xv.x * wv.x; yr[1] = xv.y * wv.y;
        yr[2] = xv.z * wv.z; yr[3] = xv.w * wv.w;
    }

    float O[4][16];
    #pragma unroll
    for (int r = 0; r < 4; r++)
        #pragma unroll
        for (int c = 0; c < 16; c++) O[r][c] = 0.f;

    float mrow[4], lrow[4];
    #pragma unroll
    for (int r = 0; r < 4; r++) { mrow[r] = -1e30f; lrow[r] = 0.f; }

    for (int j0 = 0; j0 < LL; j0 += BN) {
        __syncthreads();  // previous iteration done reading Ks/Ps

        // load K tile (padded rows)
        for (int idx = tid; idx < BN * (DD / 4); idx += 256) {
            int i = idx >> 6, d4 = idx & 63;
            float4 kv = reinterpret_cast<const float4*>(xb + (size_t)(j0 + i) * DD)[d4];
            float* kr = Ks + i * KSTRIDE + d4 * 4;
            kr[0] = kv.x; kr[1] = kv.y; kr[2] = kv.z; kr[3] = kv.w;
        }
        // su[j] = x_j . wu   (4 threads per row, shfl reduce)
        {
            int row = tid >> 2, q = tid & 3;
            float part = 0.f;
            const float4* xr = reinterpret_cast<const float4*>(xb + (size_t)(j0 + row) * DD);
            #pragma unroll
            for (int d4 = q * 16; d4 < q * 16 + 16; d4++) {
                float4 xv = xr[d4]; float4 wv = wu4[d4];
                part += xv.x * wv.x + xv.y * wv.y + xv.z * wv.z + xv.w * wv.w;
            }
            part += __shfl_xor_sync(0xffffffffu, part, 1);
            part += __shfl_xor_sync(0xffffffffu, part, 2);
            if (q == 0) su[row] = part;
        }
        __syncthreads();

        // ---- S = Y @ K^T (+ su) ----
        float acc[4][4];
        #pragma unroll
        for (int r = 0; r < 4; r++)
            #pragma unroll
            for (int c = 0; c < 4; c++) acc[r][c] = 0.f;

        #pragma unroll 4
        for (int d = 0; d < DD; d++) {
            float yv[4], kv[4];
            #pragma unroll
            for (int r = 0; r < 4; r++) yv[r] = Ys[(ty * 4 + r) * DD + d];
            #pragma unroll
            for (int c = 0; c < 4; c++) kv[c] = Ks[(tx * 4 + c) * KSTRIDE + d];
            #pragma unroll
            for (int r = 0; r < 4; r++)
                #pragma unroll
                for (int c = 0; c < 4; c++) acc[r][c] += yv[r] * kv[c];
        }
        #pragma unroll
        for (int c = 0; c < 4; c++) {
            float s = su[tx * 4 + c];
            #pragma unroll
            for (int r = 0; r < 4; r++) acc[r][c] += s;
        }

        // ---- online softmax (row stats across 16-lane tx groups) ----
        #pragma unroll
        for (int r = 0; r < 4; r++) {
            float tm = fmaxf(fmaxf(acc[r][0], acc[r][1]), fmaxf(acc[r][2], acc[r][3]));
            tm = fmaxf(tm, __shfl_xor_sync(0xffffffffu, tm, 1));
            tm = fmaxf(tm, __shfl_xor_sync(0xffffffffu, tm, 2));
            tm = fmaxf(tm, __shfl_xor_sync(0xffffffffu, tm, 4));
            tm = fmaxf(tm, __shfl_xor_sync(0xffffffffu, tm, 8));
            float mnew = fmaxf(mrow[r], tm);
            float corr = __expf(mrow[r] - mnew);
            float ls = 0.f;
            #pragma unroll
            for (int c = 0; c < 4; c++) {
                float p = __expf(acc[r][c] - mnew);
                Ps[(ty * 4 + r) * PSTRIDE + tx * 4 + c] = p;
                ls += p;
            }
            ls += __shfl_xor_sync(0xffffffffu, ls, 1);
            ls += __shfl_xor_sync(0xffffffffu, ls, 2);
            ls += __shfl_xor_sync(0xffffffffu, ls, 4);
            ls += __shfl_xor_sync(0xffffffffu, ls, 8);
            lrow[r] = lrow[r] * corr + ls;
            mrow[r] = mnew;
            #pragma unroll
            for (int c = 0; c < 16; c++) O[r][c] *= corr;
        }
        __syncthreads();

        // ---- O += P @ K ----
        #pragma unroll 2
        for (int j = 0; j < BN; j++) {
            float pv[4];
            #pragma unroll
            for (int r = 0; r < 4; r++) pv[r] = Ps[(ty * 4 + r) * PSTRIDE + j];
            float kv[16];
            #pragma unroll
            for (int c = 0; c < 4; c++)
                #pragma unroll
                for (int q = 0; q < 4; q++)
                    kv[c * 4 + q] = Ks[j * KSTRIDE + tx * 4 + q + 64 * c];
            #pragma unroll
            for (int r = 0; r < 4; r++)
                #pragma unroll
                for (int cq = 0; cq < 16; cq++) O[r][cq] += pv[r] * kv[cq];
        }
    }

    // normalize + store (d = 4tx+q+64c -> float4 at d4 = tx+16c)
    #pragma unroll
    for (int r = 0; r < 4; r++) {
        float inv = 1.f / lrow[r];
        float* orow = g_attn + ((size_t)b * LL + q0 + ty * 4 + r) * DD;
        #pragma unroll
        for (int c = 0; c < 4; c++) {
            float4 v = make_float4(O[r][c * 4 + 0] * inv, O[r][c * 4 + 1] * inv,
                                   O[r][c * 4 + 2] * inv, O[r][c * 4 + 3] * inv);
            reinterpret_cast<float4*>(orow)[tx + 16 * c] = v;
        }
    }
}

// ---------------------------------------------------------------------------
// Kernel B: fused gated MLP.
//  H = [x, attn] (16384 x 512);  g_m = H @ w_m + b_m,  m=1..3
//  out = sigmoid(g2)*x + sigmoid(g3)*tanh(g1)
// grid 512 (32 rows/CTA), 256 threads. Warp w owns rows 4w..4w+3, lane ln owns
// cols ln+32c (c<8). H tile resident in smem; W streamed in 32-row chunks.
// ---------------------------------------------------------------------------
__global__ __launch_bounds__(256, 1)
void mlp_kernel(const float* __restrict__ x,
                const float* __restrict__ w1, const float* __restrict__ w2,
                const float* __restrict__ w3,
                const float* __restrict__ b1, const float* __restrict__ b2,
                const float* __restrict__ b3,
                float* __restrict__ out)
{
    extern __shared__ float sm[];
    float* Hs = sm;               // [32][512]
    float* Ws = Hs + 32 * 512;    // [32][256]

    const int row0 = blockIdx.x * 32;
    const int tid  = threadIdx.x;
    const int w    = tid >> 5;
    const int ln   = tid & 31;

    for (int idx = tid; idx < 32 * 128; idx += 256) {
        int i = idx >> 7, c4 = idx & 127;
        float4 v;
        if (c4 < 64)
            v = reinterpret_cast<const float4*>(x + (size_t)(row0 + i) * DD)[c4];
        else
            v = reinterpret_cast<const float4*>(g_attn + (size_t)(row0 + i) * DD)[c4 - 64];
        reinterpret_cast<float4*>(Hs + i * 512)[c4] = v;
    }

    float zreg[4][8], outacc[4][8];

    for (int m = 0; m < 3; m++) {
        const float* W = (m == 0) ? w1 : (m == 1) ? w2 : w3;
        float acc[4][8];
        #pragma unroll
        for (int r = 0; r < 4; r++)
            #pragma unroll
            for (int c = 0; c < 8; c++) acc[r][c] = 0.f;

        for (int k0 = 0; k0 < 512; k0 += 32) {
            __syncthreads();
            for (int idx = tid; idx < 32 * 64; idx += 256) {
                int kk = idx >> 6, n4 = idx & 63;
                reinterpret_cast<float4*>(Ws + kk * DD)[n4] =
                    reinterpret_cast<const float4*>(W + (size_t)(k0 + kk) * DD)[n4];
            }
            __syncthreads();
            #pragma unroll 4
            for (int kk = 0; kk < 32; kk++) {
                float hv[4];
                #pragma unroll
                for (int r = 0; r < 4; r++) hv[r] = Hs[(w * 4 + r) * 512 + k0 + kk];
                #pragma unroll
                for (int c = 0; c < 8; c++) {
                    float wv = Ws[kk * DD + ln + 32 * c];
                    #pragma unroll
                    for (int r = 0; r < 4; r++) acc[r][c] += hv[r] * wv;
                }
            }
        }

        if (m == 0) {
            #pragma unroll
            for (int c = 0; c < 8; c++) {
                float bv = b1[ln + 32 * c];
                #pragma unroll
                for (int r = 0; r < 4; r++) zreg[r][c] = tanhf(acc[r][c] + bv);
            }
        } else if (m == 1) {
            #pragma unroll
            for (int c = 0; c < 8; c++) {
                float bv = b2[ln + 32 * c];
                #pragma unroll
                for (int r = 0; r < 4; r++) {
                    float s = 1.f / (1.f + __expf(-(acc[r][c] + bv)));
                    outacc[r][c] = s * Hs[(w * 4 + r) * 512 + ln + 32 * c];  // x part
                }
            }
        } else {
            #pragma unroll
            for (int c = 0; c < 8; c++) {
                float bv = b3[ln + 32 * c];
                #pragma unroll
                for (int r = 0; r < 4; r++) {
                    float s = 1.f / (1.f + __expf(-(acc[r][c] + bv)));
                    outacc[r][c] += s * zreg[r][c];
                }
            }
        }
    }

    #pragma unroll
    for (int r = 0; r < 4; r++) {
        float* orow = out + (size_t)(row0 + w * 4 + r) * DD;
        #pragma unroll
        for (int c = 0; c < 8; c++) orow[ln + 32 * c] = outacc[r][c];
    }
}

// ---------------------------------------------------------------------------
extern "C" void kernel_launch(void* const* d_in, const int* in_sizes, int n_in,
                              void* d_out, int out_size)
{
    const float* x   = (const float*)d_in[0];
    const float* wia = (const float*)d_in[1];
    const float* w1  = (const float*)d_in[2];
    const float* w2  = (const float*)d_in[3];
    const float* w3  = (const float*)d_in[4];
    const float* b1  = (const float*)d_in[5];
    const float* b2  = (const float*)d_in[6];
    const float* b3  = (const float*)d_in[7];
    float* out = (float*)d_out;

    const size_t smA = (size_t)(BM * DD + BN * KSTRIDE + BM * PSTRIDE + 64) * sizeof(float);
    const size_t smB = (size_t)(32 * 512 + 32 * 256) * sizeof(float);

    cudaFuncSetAttribute(attn_kernel, cudaFuncAttributeMaxDynamicSharedMemorySize, (int)smA);
    cudaFuncSetAttribute(mlp_kernel,  cudaFuncAttributeMaxDynamicSharedMemorySize, (int)smB);

    attn_kernel<<<dim3(LL / BM, BB), 256, smA>>>(x, wia);
    mlp_kernel<<<(BB * LL) / 32, 256, smB>>>(x, w1, w2, w3, b1, b2, b3, out);
}

// round 2
// speedup vs baseline: 1.0005x; 1.0005x over previous
#include <cuda_runtime.h>

#define BB 8
#define LL 2048
#define DD 256
#define BM 64
#define BN 64

#define KSTRIDE 257   // padded K-tile row stride (floats) to break bank conflicts
#define PSTRIDE 65    // padded P-tile row stride

// 16 MB scratch for itr_attn (static device array: allocation-free)
__device__ float g_attn[(size_t)BB * LL * DD];

// ---------------------------------------------------------------------------
// Kernel A: flash-style internal attention.
//  logits A[i,j] = s_u[j] + sum_d (x_i,d * wp_d) * x_j,d      (s_m dropped:
//  it is constant along softmax axis j and cancels)
//  out = softmax_j(A) @ x
// grid (L/BM, B), 256 threads. Thread (ty=tid>>4, tx=tid&15) owns a 4x4 S
// microtile (rows 4ty+r, cols 4tx+c) and O cols d = 4tx+q+64c (q<4,c<4).
// ---------------------------------------------------------------------------
__global__ __launch_bounds__(256, 1)
void attn_kernel(const float* __restrict__ x, const float* __restrict__ w_itr)
{
    extern __shared__ float sm[];
    float* Ys = sm;                       // [64][256]
    float* Ks = Ys + BM * DD;             // [64][KSTRIDE]
    float* Ps = Ks + BN * KSTRIDE;        // [64][PSTRIDE]
    float* su = Ps + BM * PSTRIDE;        // [64]

    const int b   = blockIdx.y;
    const int q0  = blockIdx.x * BM;
    const int tid = threadIdx.x;
    const int tx  = tid & 15;
    const int ty  = tid >> 4;

    const float* xb = x + (size_t)b * LL * DD;
    const float* wu = w_itr;              // [0:D)
    const float* wp = w_itr + 2 * DD;     // [2D:3D)

    const float4* wp4 = reinterpret_cast<const float4*>(wp);
    const float4* wu4 = reinterpret_cast<const float4*>(wu);

    // Y = x_q * wp (resident for whole CTA)
    for (int idx = tid; idx < BM * (DD / 4); idx += 256) {
        int i = idx >> 6, d4 = idx & 63;
        float4 xv = reinterpret_cast<const float4*>(xb + (size_t)(q0 + i) * DD)[d4];
        float4 wv = wp4[d4];
        float* yr = Ys + i * DD + d4 * 4;
        yr[0] = xv.x * wv.x; yr[1] = xv.y * wv.y;
        yr[2] = xv.z * wv.z; yr[3] = xv.w * wv.w;
    }

    float O[4][16];
    #pragma unroll
    for (int r = 0; r < 4; r++)
        #pragma unroll
        for (int c = 0; c < 16; c++) O[r][c] = 0.f;

    float mrow[4], lrow[4];
    #pragma unroll
    for (int r = 0; r < 4; r++) { mrow[r] = -1e30f; lrow[r] = 0.f; }

    for (int j0 = 0; j0 < LL; j0 += BN) {
        __syncthreads();  // previous iteration done reading Ks/Ps

        // load K tile (padded rows)
        for (int idx = tid; idx < BN * (DD / 4); idx += 256) {
            int i = idx >> 6, d4 = idx & 63;
            float4 kv = reinterpret_cast<const float4*>(xb + (size_t)(j0 + i) * DD)[d4];
            float* kr = Ks + i * KSTRIDE + d4 * 4;
            kr[0] = kv.x; kr[1] = kv.y; kr[2] = kv.z; kr[3] = kv.w;
        }
        // su[j] = x_j . wu   (4 threads per row, shfl reduce)
        {
            int row = tid >> 2, q = tid & 3;
            float part = 0.f;
            const float4* xr = reinterpret_cast<const float4*>(xb + (size_t)(j0 + row) * DD);
            #pragma unroll
            for (int d4 = q * 16; d4 < q * 16 + 16; d4++) {
                float4 xv = xr[d4]; float4 wv = wu4[d4];
                part += xv.x * wv.x + xv.y * wv.y + xv.z * wv.z + xv.w * wv.w;
            }
            part += __shfl_xor_sync(0xffffffffu, part, 1);
            part += __shfl_xor_sync(0xffffffffu, part, 2);
            if (q == 0) su[row] = part;
        }
        __syncthreads();

        // ---- S = Y @ K^T (+ su) ----
        float acc[4][4];
        #pragma unroll
        for (int r = 0; r < 4; r++)
            #pragma unroll
            for (int c = 0; c < 4; c++) acc[r][c] = 0.f;

        #pragma unroll 4
        for (int d = 0; d < DD; d++) {
            float yv[4], kv[4];
            #pragma unroll
            for (int r = 0; r < 4; r++) yv[r] = Ys[(ty * 4 + r) * DD + d];
            #pragma unroll
            for (int c = 0; c < 4; c++) kv[c] = Ks[(tx * 4 + c) * KSTRIDE + d];
            #pragma unroll
            for (int r = 0; r < 4; r++)
                #pragma unroll
                for (int c = 0; c < 4; c++) acc[r][c] += yv[r] * kv[c];
        }
        #pragma unroll
        for (int c = 0; c < 4; c++) {
            float s = su[tx * 4 + c];
            #pragma unroll
            for (int r = 0; r < 4; r++) acc[r][c] += s;
        }

        // ---- online softmax (row stats across 16-lane tx groups) ----
        #pragma unroll
        for (int r = 0; r < 4; r++) {
            float tm = fmaxf(fmaxf(acc[r][0], acc[r][1]), fmaxf(acc[r][2], acc[r][3]));
            tm = fmaxf(tm, __shfl_xor_sync(0xffffffffu, tm, 1));
            tm = fmaxf(tm, __shfl_xor_sync(0xffffffffu, tm, 2));
            tm = fmaxf(tm, __shfl_xor_sync(0xffffffffu, tm, 4));
            tm = fmaxf(tm, __shfl_xor_sync(0xffffffffu, tm, 8));
            float mnew = fmaxf(mrow[r], tm);
            float corr = __expf(mrow[r] - mnew);
            float ls = 0.f;
            #pragma unroll
            for (int c = 0; c < 4; c++) {
                float p = __expf(acc[r][c] - mnew);
                Ps[(ty * 4 + r) * PSTRIDE + tx * 4 + c] = p;
                ls += p;
            }
            ls += __shfl_xor_sync(0xffffffffu, ls, 1);
            ls += __shfl_xor_sync(0xffffffffu, ls, 2);
            ls += __shfl_xor_sync(0xffffffffu, ls, 4);
            ls += __shfl_xor_sync(0xffffffffu, ls, 8);
            lrow[r] = lrow[r] * corr + ls;
            mrow[r] = mnew;
            #pragma unroll
            for (int c = 0; c < 16; c++) O[r][c] *= corr;
        }
        __syncthreads();

        // ---- O += P @ K ----
        #pragma unroll 2
        for (int j = 0; j < BN; j++) {
            float pv[4];
            #pragma unroll
            for (int r = 0; r < 4; r++) pv[r] = Ps[(ty * 4 + r) * PSTRIDE + j];
            float kv[16];
            #pragma unroll
            for (int c = 0; c < 4; c++)
                #pragma unroll
                for (int q = 0; q < 4; q++)
                    kv[c * 4 + q] = Ks[j * KSTRIDE + tx * 4 + q + 64 * c];
            #pragma unroll
            for (int r = 0; r < 4; r++)
                #pragma unroll
                for (int cq = 0; cq < 16; cq++) O[r][cq] += pv[r] * kv[cq];
        }
    }

    // normalize + store (d = 4tx+q+64c -> float4 at d4 = tx+16c)
    #pragma unroll
    for (int r = 0; r < 4; r++) {
        float inv = 1.f / lrow[r];
        float* orow = g_attn + ((size_t)b * LL + q0 + ty * 4 + r) * DD;
        #pragma unroll
        for (int c = 0; c < 4; c++) {
            float4 v = make_float4(O[r][c * 4 + 0] * inv, O[r][c * 4 + 1] * inv,
                                   O[r][c * 4 + 2] * inv, O[r][c * 4 + 3] * inv);
            reinterpret_cast<float4*>(orow)[tx + 16 * c] = v;
        }
    }
}

// ---------------------------------------------------------------------------
// Kernel B: fused gated MLP.
//  H = [x, attn] (16384 x 512);  g_m = H @ w_m + b_m,  m=1..3
//  out = sigmoid(g2)*x + sigmoid(g3)*tanh(g1)
// grid 512 (32 rows/CTA), 256 threads. Warp w owns rows 4w..4w+3, lane ln owns
// cols ln+32c (c<8). H tile resident in smem; W streamed in 32-row chunks.
// ---------------------------------------------------------------------------
__global__ __launch_bounds__(256, 1)
void mlp_kernel(const float* __restrict__ x,
                const float* __restrict__ w1, const float* __restrict__ w2,
                const float* __restrict__ w3,
                const float* __restrict__ b1, const float* __restrict__ b2,
                const float* __restrict__ b3,
                float* __restrict__ out)
{
    extern __shared__ float sm[];
    float* Hs = sm;               // [32][512]
    float* Ws = Hs + 32 * 512;    // [32][256]

    const int row0 = blockIdx.x * 32;
    const int tid  = threadIdx.x;
    const int w    = tid >> 5;
    const int ln   = tid & 31;

    for (int idx = tid; idx < 32 * 128; idx += 256) {
        int i = idx >> 7, c4 = idx & 127;
        float4 v;
        if (c4 < 64)
            v = reinterpret_cast<const float4*>(x + (size_t)(row0 + i) * DD)[c4];
        else
            v = reinterpret_cast<const float4*>(g_attn + (size_t)(row0 + i) * DD)[c4 - 64];
        reinterpret_cast<float4*>(Hs + i * 512)[c4] = v;
    }

    float zreg[4][8], outacc[4][8];

    for (int m = 0; m < 3; m++) {
        const float* W = (m == 0) ? w1 : (m == 1) ? w2 : w3;
        float acc[4][8];
        #pragma unroll
        for (int r = 0; r < 4; r++)
            #pragma unroll
            for (int c = 0; c < 8; c++) acc[r][c] = 0.f;

        for (int k0 = 0; k0 < 512; k0 += 32) {
            __syncthreads();
            for (int idx = tid; idx < 32 * 64; idx += 256) {
                int kk = idx >> 6, n4 = idx & 63;
                reinterpret_cast<float4*>(Ws + kk * DD)[n4] =
                    reinterpret_cast<const float4*>(W + (size_t)(k0 + kk) * DD)[n4];
            }
            __syncthreads();
            #pragma unroll 4
            for (int kk = 0; kk < 32; kk++) {
                float hv[4];
                #pragma unroll
                for (int r = 0; r < 4; r++) hv[r] = Hs[(w * 4 + r) * 512 + k0 + kk];
                #pragma unroll
                for (int c = 0; c < 8; c++) {
                    float wv = Ws[kk * DD + ln + 32 * c];
                    #pragma unroll
                    for (int r = 0; r < 4; r++) acc[r][c] += hv[r] * wv;
                }
            }
        }

        if (m == 0) {
            #pragma unroll
            for (int c = 0; c < 8; c++) {
                float bv = b1[ln + 32 * c];
                #pragma unroll
                for (int r = 0; r < 4; r++) zreg[r][c] = tanhf(acc[r][c] + bv);
            }
        } else if (m == 1) {
            #pragma unroll
            for (int c = 0; c < 8; c++) {
                float bv = b2[ln + 32 * c];
                #pragma unroll
                for (int r = 0; r < 4; r++) {
                    float s = 1.f / (1.f + __expf(-(acc[r][c] + bv)));
                    outacc[r][c] = s * Hs[(w * 4 + r) * 512 + ln + 32 * c];  // x part
                }
            }
        } else {
            #pragma unroll
            for (int c = 0; c < 8; c++) {
                float bv = b3[ln + 32 * c];
                #pragma unroll
                for (int r = 0; r < 4; r++) {
                    float s = 1.f / (1.f + __expf(-(acc[r][c] + bv)));
                    outacc[r][c] += s * zreg[r][c];
                }
            }
        }
    }

    #pragma unroll
    for (int r = 0; r < 4; r++) {
        float* orow = out + (size_t)(row0 + w * 4 + r) * DD;
        #pragma unroll
        for (int c = 0; c < 8; c++) orow[ln + 32 * c] = outacc[r][c];
    }
}

// ---------------------------------------------------------------------------
extern "C" void kernel_launch(void* const* d_in, const int* in_sizes, int n_in,
                              void* d_out, int out_size)
{
    const float* x   = (const float*)d_in[0];
    const float* wia = (const float*)d_in[1];
    const float* w1  = (const float*)d_in[2];
    const float* w2  = (const float*)d_in[3];
    const float* w3  = (const float*)d_in[4];
    const float* b1  = (const float*)d_in[5];
    const float* b2  = (const float*)d_in[6];
    const float* b3  = (const float*)d_in[7];
    float* out = (float*)d_out;

    const size_t smA = (size_t)(BM * DD + BN * KSTRIDE + BM * PSTRIDE + 64) * sizeof(float);
    const size_t smB = (size_t)(32 * 512 + 32 * 256) * sizeof(float);

    cudaFuncSetAttribute(attn_kernel, cudaFuncAttributeMaxDynamicSharedMemorySize, (int)smA);
    cudaFuncSetAttribute(mlp_kernel,  cudaFuncAttributeMaxDynamicSharedMemorySize, (int)smB);

    attn_kernel<<<dim3(LL / BM, BB), 256, smA>>>(x, wia);
    mlp_kernel<<<(BB * LL) / 32, 256, smB>>>(x, w1, w2, w3, b1, b2, b3, out);
}

// round 4
// speedup vs baseline: 1.9112x; 1.9101x over previous
#include <cuda_runtime.h>
#include <cstdint>

#define BB 8
#define LL 2048
#define DD 256
#define BM 64
#define BN 64
#define NTILES (LL / BN)

#define LDK 260   // Y/K smem row stride (floats): (4*row+col)%32 conflict-free
#define LDP 68    // P smem row stride

// smem float offsets
#define SU_OFF 0
#define LS_OFF 64
#define Y_OFF  320
#define K_OFF  (Y_OFF + BM * LDK)
#define P_OFF  (K_OFF + BN * LDK)
#define SM_FLOATS (P_OFF + BM * LDP)

__device__ float g_attn[(size_t)BB * LL * DD];

__device__ __forceinline__ uint32_t f2tf(float f) {
    uint32_t u; asm("cvt.rna.tf32.f32 %0, %1;" : "=r"(u) : "f"(f)); return u;
}
__device__ __forceinline__ void mma_tf32(float* c, const uint32_t* a, const uint32_t* b) {
    asm volatile("mma.sync.aligned.m16n8k8.row.col.f32.tf32.tf32.f32 "
        "{%0,%1,%2,%3}, {%4,%5,%6,%7}, {%8,%9}, {%0,%1,%2,%3};"
        : "+f"(c[0]), "+f"(c[1]), "+f"(c[2]), "+f"(c[3])
        : "r"(a[0]), "r"(a[1]), "r"(a[2]), "r"(a[3]), "r"(b[0]), "r"(b[1]));
}

// ---------------------------------------------------------------------------
// Flash attention, tf32 mma.sync.
//  S[i,j] = sum_d Y[i,d]K[j,d];  P = exp(S + su[j]);  O += P @ K;  O /= rowsum
// Warp w: wr=w&1 (rows 32wr..), wc=w>>1. S tile: 32x16 @ cols 16wc.
// O tile: 32x64 @ cols 64wc. lane: g=lane>>2, t=lane&3.
// ---------------------------------------------------------------------------
__global__ __launch_bounds__(256, 1)
void attn_kernel(const float* __restrict__ x, const float* __restrict__ w_itr)
{
    extern __shared__ float sm[];
    float*    su_s = sm + SU_OFF;
    float*    ls_s = sm + LS_OFF;
    uint32_t* Ys = (uint32_t*)(sm + Y_OFF);
    uint32_t* Ks = (uint32_t*)(sm + K_OFF);
    uint32_t* Ps = (uint32_t*)(sm + P_OFF);

    const int tid = threadIdx.x, w = tid >> 5, lane = tid & 31;
    const int g = lane >> 2, t = lane & 3;
    const int wr = w & 1, wc = w >> 1;
    const int b = blockIdx.y, q0 = blockIdx.x * BM;

    const float* xb = x + (size_t)b * LL * DD;
    const float4* wu4 = (const float4*)w_itr;
    const float4* wp4 = (const float4*)(w_itr + 2 * DD);

    // Y = tf32(x_q * wp)
    for (int idx = tid; idx < BM * (DD / 4); idx += 256) {
        int i = idx >> 6, d4 = idx & 63;
        float4 xv = ((const float4*)(xb + (size_t)(q0 + i) * DD))[d4];
        float4 wv = wp4[d4];
        uint32_t* yr = Ys + i * LDK + d4 * 4;
        yr[0] = f2tf(xv.x * wv.x); yr[1] = f2tf(xv.y * wv.y);
        yr[2] = f2tf(xv.z * wv.z); yr[3] = f2tf(xv.w * wv.w);
    }

    float accO[2][8][4];
    #pragma unroll
    for (int mi = 0; mi < 2; mi++)
        #pragma unroll
        for (int ni = 0; ni < 8; ni++)
            #pragma unroll
            for (int q = 0; q < 4; q++) accO[mi][ni][q] = 0.f;
    float lsum[2][2] = {{0.f, 0.f}, {0.f, 0.f}};

    for (int tt = 0; tt < NTILES; tt++) {
        const int j0 = tt * BN;
        __syncthreads();   // prior PV done with Ks/Ps

        // K tile -> tf32 smem
        for (int idx = tid; idx < BN * (DD / 4); idx += 256) {
            int i = idx >> 6, d4 = idx & 63;
            float4 kv = ((const float4*)(xb + (size_t)(j0 + i) * DD))[d4];
            uint32_t* kr = Ks + i * LDK + d4 * 4;
            kr[0] = f2tf(kv.x); kr[1] = f2tf(kv.y);
            kr[2] = f2tf(kv.z); kr[3] = f2tf(kv.w);
        }
        // su[j] = x_j . wu  (4 threads/row, fp32 from gmem)
        {
            int row = tid >> 2, q = tid & 3;
            float part = 0.f;
            const float4* xr = (const float4*)(xb + (size_t)(j0 + row) * DD);
            #pragma unroll
            for (int d4 = q * 16; d4 < q * 16 + 16; d4++) {
                float4 a = xr[d4], ww = wu4[d4];
                part += a.x * ww.x + a.y * ww.y + a.z * ww.z + a.w * ww.w;
            }
            part += __shfl_xor_sync(0xffffffffu, part, 1);
            part += __shfl_xor_sync(0xffffffffu, part, 2);
            if (q == 0) su_s[row] = part;
        }
        __syncthreads();

        // ---- S = Y @ K^T : per-warp 32x16, k=256 ----
        float accS[2][2][4];
        #pragma unroll
        for (int mi = 0; mi < 2; mi++)
            #pragma unroll
            for (int ni = 0; ni < 2; ni++)
                #pragma unroll
                for (int q = 0; q < 4; q++) accS[mi][ni][q] = 0.f;

        #pragma unroll 4
        for (int d0 = 0; d0 < DD; d0 += 8) {
            uint32_t a[2][4], bb[2][2];
            #pragma unroll
            for (int mi = 0; mi < 2; mi++) {
                const uint32_t* yr = Ys + (wr * 32 + mi * 16 + g) * LDK + d0 + t;
                a[mi][0] = yr[0];
                a[mi][1] = yr[8 * LDK];
                a[mi][2] = yr[4];
                a[mi][3] = yr[8 * LDK + 4];
            }
            #pragma unroll
            for (int ni = 0; ni < 2; ni++) {
                const uint32_t* kr = Ks + (wc * 16 + ni * 8 + g) * LDK + d0 + t;
                bb[ni][0] = kr[0];
                bb[ni][1] = kr[4];
            }
            #pragma unroll
            for (int mi = 0; mi < 2; mi++)
                #pragma unroll
                for (int ni = 0; ni < 2; ni++) mma_tf32(accS[mi][ni], a[mi], bb[ni]);
        }

        // ---- epilogue: P = tf32(exp(S + su)), accumulate row sums ----
        #pragma unroll
        for (int mi = 0; mi < 2; mi++) {
            const int row0 = wr * 32 + mi * 16 + g;
            #pragma unroll
            for (int ni = 0; ni < 2; ni++) {
                const int c01 = wc * 16 + ni * 8 + 2 * t;
                const float s0 = su_s[c01], s1 = su_s[c01 + 1];
                uint32_t u0 = f2tf(__expf(accS[mi][ni][0] + s0));
                uint32_t u1 = f2tf(__expf(accS[mi][ni][1] + s1));
                uint32_t u2 = f2tf(__expf(accS[mi][ni][2] + s0));
                uint32_t u3 = f2tf(__expf(accS[mi][ni][3] + s1));
                lsum[mi][0] += __uint_as_float(u0) + __uint_as_float(u1);
                lsum[mi][1] += __uint_as_float(u2) + __uint_as_float(u3);
                *(uint2*)(Ps + row0 * LDP + c01)       = make_uint2(u0, u1);
                *(uint2*)(Ps + (row0 + 8) * LDP + c01) = make_uint2(u2, u3);
            }
        }
        __syncthreads();  // P visible to all warps

        // ---- O += P @ K : per-warp 32 rows x 64 cols (cols 64wc), k=64 ----
        #pragma unroll 2
        for (int jj = 0; jj < BN; jj += 8) {
            uint32_t a[2][4];
            #pragma unroll
            for (int mi = 0; mi < 2; mi++) {
                const uint32_t* pr = Ps + (wr * 32 + mi * 16 + g) * LDP + jj + t;
                a[mi][0] = pr[0];
                a[mi][1] = pr[8 * LDP];
                a[mi][2] = pr[4];
                a[mi][3] = pr[8 * LDP + 4];
            }
            #pragma unroll
            for (int ni = 0; ni < 8; ni++) {
                uint32_t bb[2];
                const uint32_t* kr = Ks + (jj + t) * LDK + wc * 64 + ni * 8 + g;
                bb[0] = kr[0];
                bb[1] = kr[4 * LDK];
                #pragma unroll
                for (int mi = 0; mi < 2; mi++) mma_tf32(accO[mi][ni], a[mi], bb);
            }
        }
    }

    // ---- reduce row sums across t, then across wc warps ----
    #pragma unroll
    for (int mi = 0; mi < 2; mi++)
        #pragma unroll
        for (int rh = 0; rh < 2; rh++) {
            float v = lsum[mi][rh];
            v += __shfl_xor_sync(0xffffffffu, v, 1);
            v += __shfl_xor_sync(0xffffffffu, v, 2);
            lsum[mi][rh] = v;
        }
    if (t == 0) {
        #pragma unroll
        for (int mi = 0; mi < 2; mi++)
            #pragma unroll
            for (int rh = 0; rh < 2; rh++)
                ls_s[wc * 64 + wr * 32 + mi * 16 + rh * 8 + g] = lsum[mi][rh];
    }
    __syncthreads();

    // ---- normalize + store O ----
    #pragma unroll
    for (int mi = 0; mi < 2; mi++) {
        #pragma unroll
        for (int rh = 0; rh < 2; rh++) {
            const int row = wr * 32 + mi * 16 + rh * 8 + g;
            const float inv = 1.f / (ls_s[row] + ls_s[64 + row] + ls_s[128 + row] + ls_s[192 + row]);
            float* orow = g_attn + ((size_t)b * LL + q0 + row) * DD + wc * 64;
            #pragma unroll
            for (int ni = 0; ni < 8; ni++) {
                float2 v = make_float2(accO[mi][ni][rh * 2] * inv, accO[mi][ni][rh * 2 + 1] * inv);
                *(float2*)(orow + ni * 8 + 2 * t) = v;
            }
        }
    }
}

// ---------------------------------------------------------------------------
// fused gated MLP: one k-loop feeds all three GEMMs (3x H reuse per LDS)
// ---------------------------------------------------------------------------
__global__ __launch_bounds__(256, 1)
void mlp_kernel(const float* __restrict__ x,
                const float* __restrict__ w1, const float* __restrict__ w2,
                const float* __restrict__ w3,
                const float* __restrict__ b1, const float* __restrict__ b2,
                const float* __restrict__ b3,
                float* __restrict__ out)
{
    extern __shared__ float smf[];
    float* Hs = smf;               // [32][512]
    float* Ws = Hs + 32 * 512;     // [3][16][256]

    const int row0 = blockIdx.x * 32;
    const int tid  = threadIdx.x;
    const int w    = tid >> 5;
    const int ln   = tid & 31;
    const float* Wp[3] = { w1, w2, w3 };

    for (int idx = tid; idx < 32 * 128; idx += 256) {
        int i = idx >> 7, c4 = idx & 127;
        float4 v;
        if (c4 < 64) v = ((const float4*)(x + (size_t)(row0 + i) * DD))[c4];
        else         v = ((const float4*)(g_attn + (size_t)(row0 + i) * DD))[c4 - 64];
        ((float4*)(Hs + i * 512))[c4] = v;
    }

    float acc[3][4][8];
    #pragma unroll
    for (int m = 0; m < 3; m++)
        #pragma unroll
        for (int r = 0; r < 4; r++)
            #pragma unroll
            for (int c = 0; c < 8; c++) acc[m][r][c] = 0.f;

    for (int k0 = 0; k0 < 512; k0 += 16) {
        __syncthreads();
        for (int idx = tid; idx < 3072; idx += 256) {
            int m = idx >> 10, rem = idx & 1023;
            int kk = rem >> 6, n4 = rem & 63;
            ((float4*)Ws)[idx] = ((const float4*)(Wp[m] + (size_t)(k0 + kk) * DD))[n4];
        }
        __syncthreads();
        #pragma unroll 4
        for (int kk = 0; kk < 16; kk++) {
            float hv[4];
            #pragma unroll
            for (int r = 0; r < 4; r++) hv[r] = Hs[(w * 4 + r) * 512 + k0 + kk];
            #pragma unroll
            for (int m = 0; m < 3; m++)
                #pragma unroll
                for (int c = 0; c < 8; c++) {
                    float wv = Ws[m * 4096 + kk * 256 + ln + 32 * c];
                    #pragma unroll
                    for (int r = 0; r < 4; r++) acc[m][r][c] += hv[r] * wv;
                }
        }
    }

    #pragma unroll
    for (int c = 0; c < 8; c++) {
        float bv1 = b1[ln + 32 * c], bv2 = b2[ln + 32 * c], bv3 = b3[ln + 32 * c];
        #pragma unroll
        for (int r = 0; r < 4; r++) {
            float z  = tanhf(acc[0][r][c] + bv1);
            float rr = 1.f / (1.f + __expf(-(acc[1][r][c] + bv2)));
            float ff = 1.f / (1.f + __expf(-(acc[2][r][c] + bv3)));
            float xv = Hs[(w * 4 + r) * 512 + ln + 32 * c];
            out[(size_t)(row0 + w * 4 + r) * DD + ln + 32 * c] = rr * xv + ff * z;
        }
    }
}

extern "C" void kernel_launch(void* const* d_in, const int* in_sizes, int n_in,
                              void* d_out, int out_size)
{
    const float* x   = (const float*)d_in[0];
    const float* wia = (const float*)d_in[1];
    const float* w1  = (const float*)d_in[2];
    const float* w2  = (const float*)d_in[3];
    const float* w3  = (const float*)d_in[4];
    const float* b1  = (const float*)d_in[5];
    const float* b2  = (const float*)d_in[6];
    const float* b3  = (const float*)d_in[7];
    float* out = (float*)d_out;

    const size_t smA = (size_t)SM_FLOATS * sizeof(float);
    const size_t smB = (size_t)(32 * 512 + 3 * 16 * 256) * sizeof(float);

    cudaFuncSetAttribute(attn_kernel, cudaFuncAttributeMaxDynamicSharedMemorySize, (int)smA);
    cudaFuncSetAttribute(mlp_kernel,  cudaFuncAttributeMaxDynamicSharedMemorySize, (int)smB);

    attn_kernel<<<dim3(LL / BM, BB), 256, smA>>>(x, wia);
    mlp_kernel<<<(BB * LL) / 32, 256, smB>>>(x, w1, w2, w3, b1, b2, b3, out);
}

// round 7
// speedup vs baseline: 4.7799x; 2.5010x over previous
#include <cuda_runtime.h>
#include <cstdint>

#define BB 8
#define LL 2048
#define DD 256
#define BM 64
#define BN 64
#define NT (LL / BN)

// ---- global scratch (allocation-free device arrays) ----
__device__ float    g_yf[(size_t)BB * LL * DD];     // tf32(x*wp)
__device__ float    g_h [(size_t)BB * LL * 512];    // [tf32(x) | tf32(attn)]
__device__ uint32_t g_xT[(size_t)BB * 256 * 1024];  // x^T bf16 j-pairs
__device__ float    g_su[(size_t)BB * LL];
__device__ float    g_wtf[3 * 256 * 512];           // W^T tf32 [m][n][k]

// ---- helpers ----
__device__ __forceinline__ uint32_t smem_u32(const void* p) {
    uint32_t a;
    asm("{ .reg .u64 t; cvta.to.shared.u64 t, %1; cvt.u32.u64 %0, t; }" : "=r"(a) : "l"(p));
    return a;
}
__device__ __forceinline__ uint32_t pk(float lo, float hi) {
    uint32_t r; asm("cvt.rn.bf16x2.f32 %0, %1, %2;" : "=r"(r) : "f"(hi), "f"(lo)); return r;
}
__device__ __forceinline__ float f2tf(float f) {
    uint32_t u; asm("cvt.rna.tf32.f32 %0, %1;" : "=r"(u) : "f"(f)); return __uint_as_float(u);
}
__device__ __forceinline__ void cpa16(uint32_t dst, const void* src) {
    asm volatile("cp.async.ca.shared.global [%0], [%1], 16;" :: "r"(dst), "l"(src));
}
#define CP_COMMIT() asm volatile("cp.async.commit_group;")
#define CP_WAIT0()  asm volatile("cp.async.wait_group 0;")

__device__ __forceinline__ void mma_bf16(float* c, const uint32_t* a, const uint32_t* b) {
    asm volatile("mma.sync.aligned.m16n8k16.row.col.f32.bf16.bf16.f32 "
        "{%0,%1,%2,%3}, {%4,%5,%6,%7}, {%8,%9}, {%0,%1,%2,%3};"
        : "+f"(c[0]), "+f"(c[1]), "+f"(c[2]), "+f"(c[3])
        : "r"(a[0]), "r"(a[1]), "r"(a[2]), "r"(a[3]), "r"(b[0]), "r"(b[1]));
}
__device__ __forceinline__ void mma_tf32(float* c, const uint32_t* a, const uint32_t* b) {
    asm volatile("mma.sync.aligned.m16n8k8.row.col.f32.tf32.tf32.f32 "
        "{%0,%1,%2,%3}, {%4,%5,%6,%7}, {%8,%9}, {%0,%1,%2,%3};"
        : "+f"(c[0]), "+f"(c[1]), "+f"(c[2]), "+f"(c[3])
        : "r"(a[0]), "r"(a[1]), "r"(a[2]), "r"(a[3]), "r"(b[0]), "r"(b[1]));
}

// ===========================================================================
// prep kernels
// ===========================================================================
__global__ void prep_su(const float* __restrict__ x, const float* __restrict__ w_itr) {
    int row = blockIdx.x * 8 + (threadIdx.x >> 5);
    int lane = threadIdx.x & 31;
    const float* xr = x + (size_t)row * DD;
    float s = 0.f;
    #pragma unroll
    for (int k = 0; k < 8; k++) s += xr[lane + 32 * k] * w_itr[lane + 32 * k];
    #pragma unroll
    for (int off = 16; off > 0; off >>= 1) s += __shfl_xor_sync(0xffffffffu, s, off);
    if (lane == 0) g_su[row] = s;
}

// per (b, jt, dt) 64x64 tile: emit g_yf, g_h x-half (tf32), g_xT (bf16 pairs)
__global__ void prep_pack(const float* __restrict__ x, const float* __restrict__ w_itr) {
    __shared__ float tl[64][65];
    int blk = blockIdx.x;                      // b*128 + jt*4 + dt
    int b = blk >> 7, rem = blk & 127, jt = rem >> 2, dt = rem & 3;
    int j0 = jt * 64, d0 = dt * 64;
    const float* xb = x + ((size_t)b * LL + j0) * DD + d0;
    int tid = threadIdx.x;
    #pragma unroll
    for (int p = 0; p < 4; p++) {
        int idx = tid + p * 256;
        int r = idx >> 4, c4 = idx & 15;
        float4 v = *(const float4*)(xb + (size_t)r * DD + c4 * 4);
        tl[r][c4 * 4 + 0] = v.x; tl[r][c4 * 4 + 1] = v.y;
        tl[r][c4 * 4 + 2] = v.z; tl[r][c4 * 4 + 3] = v.w;
    }
    __syncthreads();
    const float* wp = w_itr + 2 * DD;
    #pragma unroll
    for (int p = 0; p < 4; p++) {
        int idx = tid + p * 256;
        int r = idx >> 4, c4 = idx & 15;
        float a0 = tl[r][c4 * 4 + 0], a1 = tl[r][c4 * 4 + 1];
        float a2 = tl[r][c4 * 4 + 2], a3 = tl[r][c4 * 4 + 3];
        float4 y, h;
        y.x = f2tf(a0 * wp[d0 + c4 * 4 + 0]); y.y = f2tf(a1 * wp[d0 + c4 * 4 + 1]);
        y.z = f2tf(a2 * wp[d0 + c4 * 4 + 2]); y.w = f2tf(a3 * wp[d0 + c4 * 4 + 3]);
        h.x = f2tf(a0); h.y = f2tf(a1); h.z = f2tf(a2); h.w = f2tf(a3);
        *(float4*)(g_yf + ((size_t)b * LL + j0 + r) * DD + d0 + c4 * 4) = y;
        *(float4*)(g_h  + ((size_t)b * LL + j0 + r) * 512 + d0 + c4 * 4) = h;
    }
    #pragma unroll
    for (int p = 0; p < 8; p++) {
        int idx = tid + p * 256;
        int dl = idx >> 5, jw = idx & 31;
        g_xT[((size_t)b * 256 + d0 + dl) * 1024 + (j0 >> 1) + jw] =
            pk(tl[2 * jw][dl], tl[2 * jw + 1][dl]);
    }
}

// W^T tf32: g_wtf[m][n][k] = tf32(W_m[k][n])
__global__ void prep_w(const float* __restrict__ w1, const float* __restrict__ w2,
                       const float* __restrict__ w3) {
    __shared__ float tl[64][65];
    int blk = blockIdx.x;                        // m*32 + kt*4 + nt
    int m = blk >> 5, rem = blk & 31, kt = rem >> 2, nt = rem & 3;
    int k0 = kt * 64, n0 = nt * 64;
    const float* W = (m == 0) ? w1 : (m == 1) ? w2 : w3;
    int tid = threadIdx.x;
    #pragma unroll
    for (int p = 0; p < 4; p++) {
        int idx = tid + p * 256;
        int r = idx >> 4, c4 = idx & 15;
        float4 v = *(const float4*)(W + (size_t)(k0 + r) * DD + n0 + c4 * 4);
        tl[r][c4 * 4 + 0] = v.x; tl[r][c4 * 4 + 1] = v.y;
        tl[r][c4 * 4 + 2] = v.z; tl[r][c4 * 4 + 3] = v.w;
    }
    __syncthreads();
    #pragma unroll
    for (int p = 0; p < 4; p++) {
        int idx = tid + p * 256;
        int nl = idx >> 4, kc4 = idx & 15;
        float4 o;
        o.x = f2tf(tl[kc4 * 4 + 0][nl]); o.y = f2tf(tl[kc4 * 4 + 1][nl]);
        o.z = f2tf(tl[kc4 * 4 + 2][nl]); o.w = f2tf(tl[kc4 * 4 + 3][nl]);
        *(float4*)(g_wtf + ((size_t)m * 256 + n0 + nl) * 512 + k0 + kc4 * 4) = o;
    }
}

// ===========================================================================
// attention: S = Y@X^T tf32 (+su), P = bf16(exp(S)) [bounded, no max-sub],
// O^T += X^T @ P^T bf16; normalize; store tf32 to g_h attn-half.
// ===========================================================================
#define A_SU  0        // [2][64] f32
#define A_INV 512
#define A_LSP 768
#define A_YS  1792     // [64][260] f32
#define A_KS  68352    // [64][260] f32 (single buffer, plain loads)
#define A_KT  134912   // [2][256][36] u32 (cp.async double buffer)
#define A_PS  208640   // [64][36] u32
#define A_END 217856

__global__ __launch_bounds__(256, 1) void attn_kernel() {
    extern __shared__ char smem[];
    const uint32_t sb = smem_u32(smem);
    float* su_s  = (float*)(smem + A_SU);
    float* inv_s = (float*)(smem + A_INV);
    float* lsp   = (float*)(smem + A_LSP);
    const uint32_t* Ysw = (const uint32_t*)(smem + A_YS);
    const uint32_t* Ksw = (const uint32_t*)(smem + A_KS);
    const uint32_t* Ktw = (const uint32_t*)(smem + A_KT);
    uint32_t* Pw = (uint32_t*)(smem + A_PS);

    const int tid = threadIdx.x, w = tid >> 5, lane = tid & 31;
    const int g = lane >> 2, t = lane & 3;
    const int wsr = w & 1, wsc = w >> 1;      // S grid 2x4
    const int wor = w & 3, woc = w >> 2;      // PV grid 4x2
    const int b = blockIdx.y, q0 = blockIdx.x * BM;
    const int bbase = b * LL;

    // cp.async: Kt(0) + su(0)  (the only async pattern; R5-proven)
    #pragma unroll
    for (int p = 0; p < 8; p++) {
        int idx = tid + p * 256;
        int d = idx >> 3, c = idx & 7;
        cpa16(sb + A_KT + (d * 36 + c * 4) * 4,
              &g_xT[((size_t)(b * 256 + d)) * 1024 + c * 4]);
    }
    if (tid < 16) cpa16(sb + A_SU + tid * 16, &g_su[bbase + tid * 4]);
    CP_COMMIT();

    // plain-load Y (tf32 from g_yf)
    #pragma unroll
    for (int p = 0; p < 16; p++) {
        int idx = tid + p * 256;
        int r = idx >> 6, c4 = idx & 63;
        float4 v = *(const float4*)(g_yf + ((size_t)(bbase + q0 + r)) * DD + c4 * 4);
        *(float4*)(smem + A_YS + (r * 260 + c4 * 4) * 4) = v;
    }

    float accO[4][4][4];
    #pragma unroll
    for (int mi = 0; mi < 4; mi++)
        #pragma unroll
        for (int ni = 0; ni < 4; ni++)
            #pragma unroll
            for (int q = 0; q < 4; q++) accO[mi][ni][q] = 0.f;
    float lsum[2][2] = {{0.f, 0.f}, {0.f, 0.f}};

    for (int tt = 0; tt < NT; tt++) {
        CP_WAIT0();
        __syncthreads();                 // Kt(tt)/su(tt) ready; prior PV + epilogue done
        const int buf = tt & 1;

        if (tt < NT - 1) {               // prefetch Kt(t+1)/su(t+1) into other buffer
            const int nb = (tt + 1) & 1, j1 = (tt + 1) * BN;
            #pragma unroll
            for (int p = 0; p < 8; p++) {
                int idx = tid + p * 256;
                int d = idx >> 3, c = idx & 7;
                cpa16(sb + A_KT + nb * 36864 + (d * 36 + c * 4) * 4,
                      &g_xT[((size_t)(b * 256 + d)) * 1024 + (j1 >> 1) + c * 4]);
            }
            if (tid < 16) cpa16(sb + A_SU + nb * 256 + tid * 16, &g_su[bbase + j1 + tid * 4]);
            CP_COMMIT();
        }

        // plain-load K(tt): tf32 x rows from g_h x-half
        {
            const int j0 = tt * BN;
            #pragma unroll
            for (int p = 0; p < 16; p++) {
                int idx = tid + p * 256;
                int r = idx >> 6, c4 = idx & 63;
                float4 v = *(const float4*)(g_h + ((size_t)(bbase + j0 + r)) * 512 + c4 * 4);
                *(float4*)(smem + A_KS + (r * 260 + c4 * 4) * 4) = v;
            }
        }
        __syncthreads();                 // K visible

        // ---- S = Y @ K^T : tf32, M=64 N=64 K=256 ----
        float accS[2][2][4];
        #pragma unroll
        for (int mi = 0; mi < 2; mi++)
            #pragma unroll
            for (int ni = 0; ni < 2; ni++)
                #pragma unroll
                for (int q = 0; q < 4; q++) accS[mi][ni][q] = 0.f;
        #pragma unroll 8
        for (int ks = 0; ks < 32; ks++) {
            const int d0 = ks * 8;
            uint32_t a[2][4], bf[2][2];
            #pragma unroll
            for (int mi = 0; mi < 2; mi++) {
                const uint32_t* yp = Ysw + (wsr * 32 + mi * 16 + g) * 260 + d0 + t;
                a[mi][0] = yp[0]; a[mi][1] = yp[8 * 260];
                a[mi][2] = yp[4]; a[mi][3] = yp[8 * 260 + 4];
            }
            #pragma unroll
            for (int ni = 0; ni < 2; ni++) {
                const uint32_t* kp = Ksw + (wsc * 16 + ni * 8 + g) * 260 + d0 + t;
                bf[ni][0] = kp[0]; bf[ni][1] = kp[4];
            }
            #pragma unroll
            for (int mi = 0; mi < 2; mi++)
                #pragma unroll
                for (int ni = 0; ni < 2; ni++) mma_tf32(accS[mi][ni], a[mi], bf[ni]);
        }

        // ---- epilogue: P = bf16(exp(S + su)), row sums ----
        #pragma unroll
        for (int mi = 0; mi < 2; mi++)
            #pragma unroll
            for (int ni = 0; ni < 2; ni++) {
                const int c01 = wsc * 16 + ni * 8 + 2 * t;
                const float s0 = su_s[buf * 64 + c01], s1 = su_s[buf * 64 + c01 + 1];
                float p0 = __expf(accS[mi][ni][0] + s0);
                float p1 = __expf(accS[mi][ni][1] + s1);
                float p2 = __expf(accS[mi][ni][2] + s0);
                float p3 = __expf(accS[mi][ni][3] + s1);
                lsum[mi][0] += p0 + p1;
                lsum[mi][1] += p2 + p3;
                const int row = wsr * 32 + mi * 16 + g;
                const int jw = wsc * 8 + ni * 4 + t;
                Pw[row * 36 + jw]       = pk(p0, p1);
                Pw[(row + 8) * 36 + jw] = pk(p2, p3);
            }
        __syncthreads();                 // P visible

        // ---- O^T += K^T @ P^T : bf16, M=256(d) N=64(i) K=64(j) ----
        const uint32_t* Tb = Ktw + buf * 9216;
        #pragma unroll
        for (int kj = 0; kj < 4; kj++) {
            const int jw0 = kj * 8;
            uint32_t a[4][4];
            #pragma unroll
            for (int mi = 0; mi < 4; mi++) {
                const uint32_t* tp = Tb + (wor * 64 + mi * 16 + g) * 36 + jw0 + t;
                a[mi][0] = tp[0]; a[mi][1] = tp[8 * 36];
                a[mi][2] = tp[4]; a[mi][3] = tp[8 * 36 + 4];
            }
            #pragma unroll
            for (int ni = 0; ni < 4; ni++) {
                const uint32_t* pp = Pw + (woc * 32 + ni * 8 + g) * 36 + jw0 + t;
                uint32_t bf[2] = { pp[0], pp[4] };
                #pragma unroll
                for (int mi = 0; mi < 4; mi++) mma_bf16(accO[mi][ni], a[mi], bf);
            }
        }
    }

    // ---- row-sum reduce ----
    #pragma unroll
    for (int mi = 0; mi < 2; mi++)
        #pragma unroll
        for (int rh = 0; rh < 2; rh++) {
            float v = lsum[mi][rh];
            v += __shfl_xor_sync(0xffffffffu, v, 1);
            v += __shfl_xor_sync(0xffffffffu, v, 2);
            if (t == 0) lsp[wsc * 64 + wsr * 32 + mi * 16 + rh * 8 + g] = v;
        }
    __syncthreads();
    if (tid < 64)
        inv_s[tid] = 1.f / (lsp[tid] + lsp[64 + tid] + lsp[128 + tid] + lsp[192 + tid]);
    __syncthreads();

    // ---- normalize, tf32-round, transpose via shfl, store to g_h attn-half ----
    const bool even = ((g & 1) == 0);
    #pragma unroll
    for (int mi = 0; mi < 4; mi++)
        #pragma unroll
        for (int ni = 0; ni < 4; ni++) {
            const int iA = woc * 32 + ni * 8 + 2 * t;
            const float invA = inv_s[iA], invB = inv_s[iA + 1];
            float c0 = f2tf(accO[mi][ni][0] * invA), c1 = f2tf(accO[mi][ni][1] * invB);
            float c2 = f2tf(accO[mi][ni][2] * invA), c3 = f2tf(accO[mi][ni][3] * invB);
            float v0 = __shfl_xor_sync(0xffffffffu, c0, 4);
            float v1 = __shfl_xor_sync(0xffffffffu, c1, 4);
            float v2 = __shfl_xor_sync(0xffffffffu, c2, 4);
            float v3 = __shfl_xor_sync(0xffffffffu, c3, 4);
            float* rowA = g_h + ((size_t)(bbase + q0 + iA)) * 512 + 256;
            float* rowB = rowA + 512;
            if (even) {
                const int d2 = (wor * 32 + mi * 8 + (g >> 1)) * 2;
                *(float2*)(rowA + d2) = make_float2(c0, v0);
                *(float2*)(rowB + d2) = make_float2(c1, v1);
            } else {
                const int d2 = (wor * 32 + mi * 8 + ((g + 7) >> 1)) * 2;
                *(float2*)(rowA + d2) = make_float2(v2, c2);
                *(float2*)(rowB + d2) = make_float2(v3, c3);
            }
        }
}

// ===========================================================================
// MLP tf32, fully streamed: H chunks [64][32] + W chunks [384][32],
// double-buffered (proven loop-top pattern). grid (256, 2), 256 thr.
// ===========================================================================
#define M_HS 0          // [2][64][36] f32 = 18432
#define M_WS 18432      // [2][384][36] f32 = 110592
#define M_END 129024

__global__ __launch_bounds__(256, 1)
void mlp_kernel(const float* __restrict__ x,
                const float* __restrict__ b1, const float* __restrict__ b2,
                const float* __restrict__ b3, float* __restrict__ out)
{
    extern __shared__ char smem[];
    const uint32_t sb = smem_u32(smem);
    const uint32_t* Hw = (const uint32_t*)(smem + M_HS);
    const uint32_t* Ww = (const uint32_t*)(smem + M_WS);

    const int tid = threadIdx.x, w = tid >> 5, lane = tid & 31;
    const int g = lane >> 2, t = lane & 3;
    const int wr = w & 1, wc = w >> 1;        // 2 x 4 warps: 32 rows x 32 cols
    const int row0 = blockIdx.x * 64, n0 = blockIdx.y * 128;

    // issue chunk 0 (H k=0..31, W k=0..31)
    #pragma unroll
    for (int p = 0; p < 2; p++) {
        int idx = tid + p * 256;
        int r = idx >> 3, c = idx & 7;
        cpa16(sb + M_HS + (r * 36 + c * 4) * 4,
              &g_h[((size_t)(row0 + r)) * 512 + c * 4]);
    }
    #pragma unroll
    for (int p = 0; p < 12; p++) {
        int idx = tid + p * 256;
        int m = idx >> 10, rem = idx & 1023;
        int n = rem >> 3, c = rem & 7;
        cpa16(sb + M_WS + ((m * 128 + n) * 36 + c * 4) * 4,
              &g_wtf[((size_t)m * 256 + n0 + n) * 512 + c * 4]);
    }
    CP_COMMIT();

    float acc[3][2][4][4];
    #pragma unroll
    for (int m = 0; m < 3; m++)
        #pragma unroll
        for (int mi = 0; mi < 2; mi++)
            #pragma unroll
            for (int ni = 0; ni < 4; ni++)
                #pragma unroll
                for (int q = 0; q < 4; q++) acc[m][mi][ni][q] = 0.f;

    for (int s = 0; s < 16; s++) {
        CP_WAIT0();
        __syncthreads();
        const int buf = s & 1;

        if (s < 15) {
            const int nb = (s + 1) & 1, k1 = (s + 1) * 32;
            #pragma unroll
            for (int p = 0; p < 2; p++) {
                int idx = tid + p * 256;
                int r = idx >> 3, c = idx & 7;
                cpa16(sb + M_HS + nb * 9216 + (r * 36 + c * 4) * 4,
                      &g_h[((size_t)(row0 + r)) * 512 + k1 + c * 4]);
            }
            #pragma unroll
            for (int p = 0; p < 12; p++) {
                int idx = tid + p * 256;
                int m = idx >> 10, rem = idx & 1023;
                int n = rem >> 3, c = rem & 7;
                cpa16(sb + M_WS + nb * 55296 + ((m * 128 + n) * 36 + c * 4) * 4,
                      &g_wtf[((size_t)m * 256 + n0 + n) * 512 + k1 + c * 4]);
            }
            CP_COMMIT();
        }

        const uint32_t* Hb = Hw + buf * 2304;
        const uint32_t* Wb = Ww + buf * 13824;
        #pragma unroll
        for (int ks = 0; ks < 4; ks++) {
            uint32_t a[2][4];
            #pragma unroll
            for (int mi = 0; mi < 2; mi++) {
                const uint32_t* hp = Hb + (wr * 32 + mi * 16 + g) * 36 + ks * 8 + t;
                a[mi][0] = hp[0]; a[mi][1] = hp[8 * 36];
                a[mi][2] = hp[4]; a[mi][3] = hp[8 * 36 + 4];
            }
            #pragma unroll
            for (int m = 0; m < 3; m++)
                #pragma unroll
                for (int ni = 0; ni < 4; ni++) {
                    const uint32_t* wp2 = Wb + (m * 128 + wc * 32 + ni * 8 + g) * 36 + ks * 8 + t;
                    uint32_t bf[2] = { wp2[0], wp2[4] };
                    mma_tf32(acc[m][0][ni], a[0], bf);
                    mma_tf32(acc[m][1][ni], a[1], bf);
                }
        }
    }

    // fused epilogue (x re-read from gmem)
    #pragma unroll
    for (int mi = 0; mi < 2; mi++)
        #pragma unroll
        for (int ni = 0; ni < 4; ni++) {
            const int rloc = wr * 32 + mi * 16 + g;
            const int cc = n0 + wc * 32 + ni * 8 + 2 * t;
            const float2 bb1 = *(const float2*)(b1 + cc);
            const float2 bb2 = *(const float2*)(b2 + cc);
            const float2 bb3 = *(const float2*)(b3 + cc);
            #pragma unroll
            for (int h = 0; h < 2; h++) {
                const int rl = rloc + h * 8, i0 = h * 2;
                float z0 = tanhf(acc[0][mi][ni][i0]     + bb1.x);
                float z1 = tanhf(acc[0][mi][ni][i0 + 1] + bb1.y);
                float r0 = 1.f / (1.f + __expf(-(acc[1][mi][ni][i0]     + bb2.x)));
                float r1 = 1.f / (1.f + __expf(-(acc[1][mi][ni][i0 + 1] + bb2.y)));
                float f0 = 1.f / (1.f + __expf(-(acc[2][mi][ni][i0]     + bb3.x)));
                float f1 = 1.f / (1.f + __expf(-(acc[2][mi][ni][i0 + 1] + bb3.y)));
                const float2 xv = *(const float2*)(x + (size_t)(row0 + rl) * DD + cc);
                float2 o = make_float2(r0 * xv.x + f0 * z0, r1 * xv.y + f1 * z1);
                *(float2*)(out + (size_t)(row0 + rl) * DD + cc) = o;
            }
        }
}

// ===========================================================================
extern "C" void kernel_launch(void* const* d_in, const int* in_sizes, int n_in,
                              void* d_out, int out_size)
{
    const float* x   = (const float*)d_in[0];
    const float* wia = (const float*)d_in[1];
    const float* w1  = (const float*)d_in[2];
    const float* w2  = (const float*)d_in[3];
    const float* w3  = (const float*)d_in[4];
    const float* b1  = (const float*)d_in[5];
    const float* b2  = (const float*)d_in[6];
    const float* b3  = (const float*)d_in[7];
    float* out = (float*)d_out;

    cudaFuncSetAttribute(attn_kernel, cudaFuncAttributeMaxDynamicSharedMemorySize, A_END);
    cudaFuncSetAttribute(mlp_kernel,  cudaFuncAttributeMaxDynamicSharedMemorySize, M_END);

    prep_su  <<<LL * BB / 8, 256>>>(x, wia);
    prep_pack<<<BB * 128, 256>>>(x, wia);
    prep_w   <<<96, 256>>>(w1, w2, w3);
    attn_kernel<<<dim3(LL / BM, BB), 256, A_END>>>();
    mlp_kernel <<<dim3(BB * LL / 64, 2), 256, M_END>>>(x, b1, b2, b3, out);
}